// round 5
// baseline (speedup 1.0000x reference)
#include <cuda_runtime.h>

#define D1 200
#define NRELS 11
#define BATCHN 1024
#define NENT 100000

// ---------------- scratch (device globals; no allocation allowed) ----------------
__device__ __align__(16) float d_M[NRELS * D1 * D1];   // 11 relation matrices (1.76 MB)
__device__ __align__(16) float d_y[BATCHN * D1];
__device__ __align__(16) float d_x2[BATCHN * D1];
__device__ float d_stats[4 * D1];                      // sum0, sumsq0, sum1, sumsq1

__constant__ int c_perm[NRELS] = {8, 0, 3, 9, 4, 5, 6, 7, 1, 10, 2};

// ---------------- tiny kernels ----------------
__global__ void zero_stats_kernel() {
    int t = blockIdx.x * blockDim.x + threadIdx.x;
    if (t < 4 * D1) d_stats[t] = 0.0f;
}

// BN0 stats over gathered rows E[e1_idx]
__global__ void bn0_stats_kernel(const float* __restrict__ E, const int* __restrict__ e1_idx) {
    int j = threadIdx.x;
    if (j >= D1) return;
    float s = 0.f, ss = 0.f;
    int r0 = blockIdx.x * 8;
#pragma unroll
    for (int r = 0; r < 8; r++) {
        int e1 = e1_idx[r0 + r];
        float v = E[e1 * D1 + j];
        s += v; ss += v * v;
    }
    atomicAdd(&d_stats[j], s);
    atomicAdd(&d_stats[D1 + j], ss);
}

// Build M[rel][j][k] = sum_i R[perm[rel], i] * W[i][j][k] without materializing W.
__global__ void build_M_kernel(const float* __restrict__ R1, const float* __restrict__ R2,
                               const float* __restrict__ R3, const float* __restrict__ W1,
                               const float* __restrict__ W2, const float* __restrict__ W3) {
    int e = blockIdx.x * blockDim.x + threadIdx.x;
    if (e >= D1 * D1) return;
    int rel = blockIdx.y;
    int p = c_perm[rel];
    int j = e / D1, k = e % D1;
    int a = j < k ? j : k;
    int b = j < k ? k : j;
    int sidx = a * (2 * D1 - a + 1) / 2 + (b - a);          // symmetric (upper-tri incl diag)
    float asign = 0.f; int aoff = 0;
    if (j < k)      { asign =  1.f; aoff = (2 * D1 - j - 1) * j / 2 + (k - j) - 1; }
    else if (j > k) { asign = -1.f; aoff = (2 * D1 - k - 1) * k / 2 + (j - k) - 1; }
    float acc = 0.f;
    if (p < 3) {                 // symmetric relation: r nonzero only on first 30
#pragma unroll
        for (int s = 0; s < 30; s++) acc += R1[p * 30 + s] * W1[s * 20100 + sidx];
    } else if (p < 8) {          // antisymmetric relation: r nonzero on cols 30..59
        if (j != k) {
            float t = 0.f;
#pragma unroll
            for (int s = 0; s < 30; s++) t += R2[(p - 3) * 30 + s] * W2[s * 19900 + aoff];
            acc = asign * t;
        }
    } else {                     // free relation: full 80-dim contraction
        const float* r3 = R3 + (p - 8) * 80;
#pragma unroll
        for (int s = 0; s < 30; s++) acc += r3[s] * W1[s * 20100 + sidx];
        if (j != k) {
            float t = 0.f;
#pragma unroll
            for (int s = 0; s < 30; s++) t += r3[30 + s] * W2[s * 19900 + aoff];
            acc += asign * t;
        }
#pragma unroll
        for (int o = 0; o < 20; o++) acc += r3[60 + o] * W3[o * 40000 + e];
    }
    d_M[rel * 40000 + e] = acc;
}

// y[b] = M[r_idx[b]]^T bn0(E[e1_idx[b]]); accumulate BN1 stats.
__global__ void mid_kernel(const float* __restrict__ E, const int* __restrict__ e1_idx,
                           const int* __restrict__ r_idx,
                           const float* __restrict__ g0, const float* __restrict__ b0) {
    __shared__ float xs[D1];
    int b = blockIdx.x;
    int t = threadIdx.x;
    if (t < D1) {
        float mean = d_stats[t] * (1.f / BATCHN);
        float var  = d_stats[D1 + t] * (1.f / BATCHN) - mean * mean;
        float inv  = rsqrtf(var + 1e-5f);
        int e1 = e1_idx[b];
        xs[t] = (E[e1 * D1 + t] - mean) * inv * g0[t] + b0[t];
    }
    __syncthreads();
    if (t < D1) {
        const float* M = d_M + r_idx[b] * 40000;
        float acc = 0.f;
#pragma unroll 8
        for (int jj = 0; jj < D1; jj++) acc += M[jj * D1 + t] * xs[jj];
        d_y[b * D1 + t] = acc;
        atomicAdd(&d_stats[2 * D1 + t], acc);
        atomicAdd(&d_stats[3 * D1 + t], acc * acc);
    }
}

// x2 = bn1(y)
__global__ void x2_kernel(const float* __restrict__ g1, const float* __restrict__ b1) {
    int i = blockIdx.x * blockDim.x + threadIdx.x;
    if (i >= BATCHN * D1) return;
    int k = i % D1;
    float mean = d_stats[2 * D1 + k] * (1.f / BATCHN);
    float var  = d_stats[3 * D1 + k] * (1.f / BATCHN) - mean * mean;
    float inv  = rsqrtf(var + 1e-5f);
    d_x2[i] = (d_y[i] - mean) * inv * g1[k] + b1[k];
}

// ---------------- the big one: sigmoid(x2 @ E^T), 1024 x 100000 x 200 ----------------
// FFMA2 (fma.rn.f32x2) packed-fp32 GEMM: 128x128 tile, BK=8, 8x8 per thread (n paired).
__global__ __launch_bounds__(256, 2)
void gemm_sigmoid_kernel(const float* __restrict__ E, float* __restrict__ out) {
    __shared__ __align__(16) float As[8][128];
    __shared__ __align__(16) float Bs[8][128];

    const int t  = threadIdx.x;
    const int tx = t & 15;         // n direction, 16
    const int ty = t >> 4;         // m direction, 16
    const int m0 = blockIdx.y << 7;
    const int n0 = blockIdx.x << 7;

    // tile-load mapping: 2 threads per row, float4 each (8 k's per row)
    const int lm = t >> 1;
    const int lk = (t & 1) << 2;
    const float* aptr = d_x2 + (m0 + lm) * D1 + lk;
    const int gn = n0 + lm;
    const bool bvalid = gn < NENT;
    // clamp OOB rows to row 0 (values masked to zero) -> branch-free prefetch
    const float* bptr = E + (long long)(bvalid ? gn : 0) * D1 + lk;
    const float bmask = bvalid ? 1.0f : 0.0f;

    unsigned long long acc[8][4];
#pragma unroll
    for (int i = 0; i < 8; i++)
#pragma unroll
        for (int jp = 0; jp < 4; jp++) acc[i][jp] = 0ULL;

    float4 av = *(const float4*)(aptr);
    float4 bv = *(const float4*)(bptr);

    for (int k0 = 0; k0 < D1; k0 += 8) {
        As[lk + 0][lm] = av.x; As[lk + 1][lm] = av.y;
        As[lk + 2][lm] = av.z; As[lk + 3][lm] = av.w;
        Bs[lk + 0][lm] = bmask * bv.x; Bs[lk + 1][lm] = bmask * bv.y;
        Bs[lk + 2][lm] = bmask * bv.z; Bs[lk + 3][lm] = bmask * bv.w;
        __syncthreads();

        if (k0 + 8 < D1) {                    // prefetch next slab into registers
            av = *(const float4*)(aptr + k0 + 8);
            bv = *(const float4*)(bptr + k0 + 8);
        }

#pragma unroll
        for (int kk = 0; kk < 8; kk++) {
            unsigned long long b2[4];
#pragma unroll
            for (int jp = 0; jp < 4; jp++)
                b2[jp] = *(const unsigned long long*)(&Bs[kk][(tx << 3) + (jp << 1)]);
            float4 a0 = *(const float4*)(&As[kk][(ty << 3)]);
            float4 a1 = *(const float4*)(&As[kk][(ty << 3) + 4]);
            float af[8] = {a0.x, a0.y, a0.z, a0.w, a1.x, a1.y, a1.z, a1.w};
#pragma unroll
            for (int i = 0; i < 8; i++) {
                unsigned int au = __float_as_uint(af[i]);
                unsigned long long a2;
                asm("mov.b64 %0, {%1, %1};" : "=l"(a2) : "r"(au));
#pragma unroll
                for (int jp = 0; jp < 4; jp++)
                    asm("fma.rn.f32x2 %0, %1, %2, %0;" : "+l"(acc[i][jp]) : "l"(a2), "l"(b2[jp]));
            }
        }
        __syncthreads();
    }

    // epilogue: sigmoid + vectorized store
    const int nbase = n0 + (tx << 3);
    if (nbase < NENT) {
#pragma unroll
        for (int i = 0; i < 8; i++) {
            int m = m0 + (ty << 3) + i;
            float v[8];
#pragma unroll
            for (int jp = 0; jp < 4; jp++) {
                v[2 * jp]     = __uint_as_float((unsigned int)(acc[i][jp]));
                v[2 * jp + 1] = __uint_as_float((unsigned int)(acc[i][jp] >> 32));
            }
            float e[8];
#pragma unroll
            for (int jv = 0; jv < 8; jv++) e[jv] = __expf(-v[jv]);
#pragma unroll
            for (int jv = 0; jv < 8; jv++) v[jv] = 1.0f / (1.0f + e[jv]);
            float* op = out + (long long)m * NENT + nbase;
            *(float4*)(op)     = make_float4(v[0], v[1], v[2], v[3]);
            *(float4*)(op + 4) = make_float4(v[4], v[5], v[6], v[7]);
        }
    }
}

// ---------------- launch ----------------
extern "C" void kernel_launch(void* const* d_in, const int* in_sizes, int n_in,
                              void* d_out, int out_size) {
    const float* E  = (const float*)d_in[0];
    const float* R1 = (const float*)d_in[1];
    const float* R2 = (const float*)d_in[2];
    const float* R3 = (const float*)d_in[3];
    const float* W1 = (const float*)d_in[4];
    const float* W2 = (const float*)d_in[5];
    const float* W3 = (const float*)d_in[6];
    const float* g0 = (const float*)d_in[7];
    const float* b0 = (const float*)d_in[8];
    const float* g1 = (const float*)d_in[9];
    const float* b1 = (const float*)d_in[10];
    const int* e1_idx = (const int*)d_in[11];
    const int* r_idx  = (const int*)d_in[12];
    float* out = (float*)d_out;

    zero_stats_kernel<<<4, 256>>>();
    bn0_stats_kernel<<<BATCHN / 8, 256>>>(E, e1_idx);
    build_M_kernel<<<dim3((D1 * D1 + 255) / 256, NRELS), 256>>>(R1, R2, R3, W1, W2, W3);
    mid_kernel<<<BATCHN, 256>>>(E, e1_idx, r_idx, g0, b0);
    x2_kernel<<<(BATCHN * D1 + 255) / 256, 256>>>(g1, b1);
    gemm_sigmoid_kernel<<<dim3((NENT + 127) / 128, BATCHN / 128), 256>>>(E, out);
}

// round 8
// speedup vs baseline: 1.6502x; 1.6502x over previous
#include <cuda_runtime.h>
#include <cuda_bf16.h>
#include <cstdint>

#define D1 200
#define NRELS 11
#define BATCHN 1024
#define NENT 100000
#define NENT_PAD 100096         // 782 * 128
#define KPAD 208                // 13 k16 steps
#define KSTEPS 13
#define NTILES 782
#define MTILES 8
#define ROWB 416                // KPAD * 2 bytes per gmem row

// ---------------- scratch (device globals; no allocation allowed) ----------------
__device__ __align__(16) float d_M[NRELS * D1 * D1];
__device__ __align__(16) float d_y[BATCHN * D1];
__device__ __align__(16) float d_x2[BATCHN * D1];
__device__ float d_stats[4 * D1];

__device__ __align__(16) __nv_bfloat16 d_Ahi[BATCHN * KPAD];
__device__ __align__(16) __nv_bfloat16 d_Alo[BATCHN * KPAD];
__device__ __align__(16) __nv_bfloat16 d_Ehi[(size_t)NENT_PAD * KPAD];
__device__ __align__(16) __nv_bfloat16 d_Elo[(size_t)NENT_PAD * KPAD];

__constant__ int c_perm[NRELS] = {8, 0, 3, 9, 4, 5, 6, 7, 1, 10, 2};

// ---------------- PTX helpers (all generic-PTX-safe, sm_80-era) ----------------
__device__ __forceinline__ uint32_t smem_u32(const void* p) {
    uint32_t a;
    asm("{ .reg .u64 t; cvta.to.shared.u64 t, %1; cvt.u32.u64 %0, t; }" : "=r"(a) : "l"(p));
    return a;
}
__device__ __forceinline__ void cp16(uint32_t dst, const void* src) {
    asm volatile("cp.async.cg.shared.global [%0], [%1], 16;" :: "r"(dst), "l"(src) : "memory");
}
__device__ __forceinline__ void cp_commit() { asm volatile("cp.async.commit_group;" ::: "memory"); }
template <int N>
__device__ __forceinline__ void cp_wait() { asm volatile("cp.async.wait_group %0;" :: "n"(N) : "memory"); }

__device__ __forceinline__ void ldx4(uint32_t& r0, uint32_t& r1, uint32_t& r2, uint32_t& r3,
                                     uint32_t addr) {
    asm volatile("ldmatrix.sync.aligned.m8n8.x4.shared.b16 {%0,%1,%2,%3}, [%4];"
                 : "=r"(r0), "=r"(r1), "=r"(r2), "=r"(r3) : "r"(addr));
}
__device__ __forceinline__ void mma16816(float* c, const uint32_t* a, const uint32_t* b) {
    asm volatile(
        "mma.sync.aligned.m16n8k16.row.col.f32.bf16.bf16.f32 "
        "{%0,%1,%2,%3}, {%4,%5,%6,%7}, {%8,%9}, {%0,%1,%2,%3};"
        : "+f"(c[0]), "+f"(c[1]), "+f"(c[2]), "+f"(c[3])
        : "r"(a[0]), "r"(a[1]), "r"(a[2]), "r"(a[3]), "r"(b[0]), "r"(b[1]));
}

// ---------------- small kernels ----------------
__global__ void zero_stats_kernel() {
    int t = blockIdx.x * blockDim.x + threadIdx.x;
    if (t < 4 * D1) d_stats[t] = 0.0f;
}

__global__ void bn0_stats_kernel(const float* __restrict__ E, const int* __restrict__ e1_idx) {
    int j = threadIdx.x;
    if (j >= D1) return;
    float s = 0.f, ss = 0.f;
    int r0 = blockIdx.x * 8;
#pragma unroll
    for (int r = 0; r < 8; r++) {
        int e1 = e1_idx[r0 + r];
        float v = E[e1 * D1 + j];
        s += v; ss += v * v;
    }
    atomicAdd(&d_stats[j], s);
    atomicAdd(&d_stats[D1 + j], ss);
}

__global__ void build_M_kernel(const float* __restrict__ R1, const float* __restrict__ R2,
                               const float* __restrict__ R3, const float* __restrict__ W1,
                               const float* __restrict__ W2, const float* __restrict__ W3) {
    int e = blockIdx.x * blockDim.x + threadIdx.x;
    if (e >= D1 * D1) return;
    int rel = blockIdx.y;
    int p = c_perm[rel];
    int j = e / D1, k = e % D1;
    int a = j < k ? j : k;
    int b = j < k ? k : j;
    int sidx = a * (2 * D1 - a + 1) / 2 + (b - a);
    float asign = 0.f; int aoff = 0;
    if (j < k)      { asign =  1.f; aoff = (2 * D1 - j - 1) * j / 2 + (k - j) - 1; }
    else if (j > k) { asign = -1.f; aoff = (2 * D1 - k - 1) * k / 2 + (j - k) - 1; }
    float acc = 0.f;
    if (p < 3) {
#pragma unroll
        for (int s = 0; s < 30; s++) acc += R1[p * 30 + s] * W1[s * 20100 + sidx];
    } else if (p < 8) {
        if (j != k) {
            float t = 0.f;
#pragma unroll
            for (int s = 0; s < 30; s++) t += R2[(p - 3) * 30 + s] * W2[s * 19900 + aoff];
            acc = asign * t;
        }
    } else {
        const float* r3 = R3 + (p - 8) * 80;
#pragma unroll
        for (int s = 0; s < 30; s++) acc += r3[s] * W1[s * 20100 + sidx];
        if (j != k) {
            float t = 0.f;
#pragma unroll
            for (int s = 0; s < 30; s++) t += r3[30 + s] * W2[s * 19900 + aoff];
            acc += asign * t;
        }
#pragma unroll
        for (int o = 0; o < 20; o++) acc += r3[60 + o] * W3[o * 40000 + e];
    }
    d_M[rel * 40000 + e] = acc;
}

__global__ void mid_kernel(const float* __restrict__ E, const int* __restrict__ e1_idx,
                           const int* __restrict__ r_idx,
                           const float* __restrict__ g0, const float* __restrict__ b0) {
    __shared__ float xs[D1];
    int b = blockIdx.x;
    int t = threadIdx.x;
    if (t < D1) {
        float mean = d_stats[t] * (1.f / BATCHN);
        float var  = d_stats[D1 + t] * (1.f / BATCHN) - mean * mean;
        float inv  = rsqrtf(var + 1e-5f);
        int e1 = e1_idx[b];
        xs[t] = (E[e1 * D1 + t] - mean) * inv * g0[t] + b0[t];
    }
    __syncthreads();
    if (t < D1) {
        const float* M = d_M + r_idx[b] * 40000;
        float acc = 0.f;
#pragma unroll 8
        for (int jj = 0; jj < D1; jj++) acc += M[jj * D1 + t] * xs[jj];
        d_y[b * D1 + t] = acc;
        atomicAdd(&d_stats[2 * D1 + t], acc);
        atomicAdd(&d_stats[3 * D1 + t], acc * acc);
    }
}

__global__ void x2_kernel(const float* __restrict__ g1, const float* __restrict__ b1) {
    int i = blockIdx.x * blockDim.x + threadIdx.x;
    if (i >= BATCHN * D1) return;
    int k = i % D1;
    float mean = d_stats[2 * D1 + k] * (1.f / BATCHN);
    float var  = d_stats[3 * D1 + k] * (1.f / BATCHN) - mean * mean;
    float inv  = rsqrtf(var + 1e-5f);
    d_x2[i] = (d_y[i] - mean) * inv * g1[k] + b1[k];
}

// ---------------- split conversions ----------------
__global__ void convert_A_kernel() {
    int row = blockIdx.x;          // 0..1023
    int col = threadIdx.x;         // 0..255
    if (col >= KPAD) return;
    float v = (col < D1) ? d_x2[row * D1 + col] : 0.f;
    __nv_bfloat16 h = __float2bfloat16(v);
    d_Ahi[row * KPAD + col] = h;
    d_Alo[row * KPAD + col] = __float2bfloat16(v - __bfloat162float(h));
}

__global__ void convert_E_kernel(const float* __restrict__ E) {
    size_t row = blockIdx.x;       // 0..NENT_PAD-1
    int col = threadIdx.x;
    if (col >= KPAD) return;
    float v = (row < NENT && col < D1) ? E[row * D1 + col] : 0.f;
    __nv_bfloat16 h = __float2bfloat16(v);
    d_Ehi[row * KPAD + col] = h;
    d_Elo[row * KPAD + col] = __float2bfloat16(v - __bfloat162float(h));
}

__device__ __forceinline__ float sigmoidf_fast(float x) {
    return __fdividef(1.0f, 1.0f + __expf(-x));
}

// ---------------- bf16-split mma.sync GEMM + sigmoid ----------------
// CTA 128x128, 8 warps (warp grid 2m x 4n, warp tile 64x32), K = 13 x k16.
// smem per stage: Ah/Al/Bh/Bl, each 128 rows x 48B (16 bf16 + 8 pad) = 6144B.
#define NSTAGE 4
#define MAT_B  6144
#define STAGE_B (4 * MAT_B)          // 24576
#define SMEM_GEMM (NSTAGE * STAGE_B) // 98304

__global__ __launch_bounds__(256, 1)
void gemm_mma_kernel(float* __restrict__ out) {
    extern __shared__ __align__(128) char smem[];
    const uint32_t sb = smem_u32(smem);
    const int tid  = threadIdx.x;
    const int lane = tid & 31;
    const int wid  = tid >> 5;
    const int wm   = wid >> 2;       // 0..1  (64 rows each)
    const int wn   = wid & 3;        // 0..3  (32 cols each)

    const int m0 = blockIdx.y << 7;
    const int n0 = blockIdx.x << 7;

    // ---- cp.async mapping: thread -> matrix (tid>>6), 4 chunks of 16B ----
    const int mt = tid >> 6;         // 0:Ah 1:Al 2:Bh 3:Bl
    const int c0 = tid & 63;
    const char* gbase;
    {
        const char* gAh = (const char*)d_Ahi + (size_t)m0 * ROWB;
        const char* gAl = (const char*)d_Alo + (size_t)m0 * ROWB;
        const char* gBh = (const char*)d_Ehi + (size_t)n0 * ROWB;
        const char* gBl = (const char*)d_Elo + (size_t)n0 * ROWB;
        gbase = (mt == 0) ? gAh : (mt == 1) ? gAl : (mt == 2) ? gBh : gBl;
    }
    const uint32_t smat = sb + mt * MAT_B;

    auto issue = [&](int step, int slot) {
#pragma unroll
        for (int i = 0; i < 4; i++) {
            int c = c0 + 64 * i;
            int row = c >> 1, half = c & 1;
            cp16(smat + slot * STAGE_B + row * 48 + half * 16,
                 gbase + (size_t)row * ROWB + step * 32 + half * 16);
        }
        cp_commit();
    };

    // ---- ldmatrix per-lane offsets (48B rows -> conflict-free) ----
    const int g  = lane >> 3;
    const int l8 = lane & 7;
    // A x4 groups: (m0-7,k0),(m8-15,k0),(m0-7,k8),(m8-15,k8)
    const uint32_t a_off = (uint32_t)((wm * 64 + (g & 1) * 8 + l8) * 48 + (g >> 1) * 16);
    // B x4 groups: (n0-7,k0),(n0-7,k8),(n8-15,k0),(n8-15,k8)
    const uint32_t b_off = (uint32_t)(2 * MAT_B + (wn * 32 + (g >> 1) * 8 + l8) * 48 + (g & 1) * 16);

    float acc[4][4][4];
#pragma unroll
    for (int mi = 0; mi < 4; mi++)
#pragma unroll
        for (int ni = 0; ni < 4; ni++)
#pragma unroll
            for (int r = 0; r < 4; r++) acc[mi][ni][r] = 0.f;

    uint32_t ah[4][4], al[4][4], bh[4][2], bl[4][2];

    auto load_frags = [&](int slot) {
        uint32_t base = sb + slot * STAGE_B;
#pragma unroll
        for (int mi = 0; mi < 4; mi++) {
            ldx4(ah[mi][0], ah[mi][1], ah[mi][2], ah[mi][3], base + a_off + mi * 768);
            ldx4(al[mi][0], al[mi][1], al[mi][2], al[mi][3], base + MAT_B + a_off + mi * 768);
        }
#pragma unroll
        for (int p = 0; p < 2; p++) {
            ldx4(bh[2*p][0], bh[2*p][1], bh[2*p+1][0], bh[2*p+1][1], base + b_off + p * 768);
            ldx4(bl[2*p][0], bl[2*p][1], bl[2*p+1][0], bl[2*p+1][1],
                 base + MAT_B + b_off + p * 768);
        }
    };

    auto do_mma = [&]() {
#pragma unroll
        for (int mi = 0; mi < 4; mi++)
#pragma unroll
            for (int ni = 0; ni < 4; ni++) {
                mma16816(acc[mi][ni], ah[mi], bh[ni]);
                mma16816(acc[mi][ni], ah[mi], bl[ni]);
                mma16816(acc[mi][ni], al[mi], bh[ni]);
            }
    };

    // ---- pipeline: prologue 3 stages, steady wait<2>, peeled tail ----
    issue(0, 0); issue(1, 1); issue(2, 2);

    for (int i = 0; i < 11; i++) {
        cp_wait<2>();
        __syncthreads();
        load_frags(i & 3);
        if (i < 10) issue(i + 3, (i + 3) & 3);
        do_mma();
    }
    cp_wait<1>(); __syncthreads(); load_frags(11 & 3); do_mma();
    cp_wait<0>(); __syncthreads(); load_frags(12 & 3); do_mma();

    // ---- epilogue: sigmoid + float2 stores ----
    const int mrow0 = m0 + wm * 64 + (lane >> 2);
    const int ncol0 = n0 + wn * 32 + ((lane & 3) << 1);
#pragma unroll
    for (int mi = 0; mi < 4; mi++) {
#pragma unroll
        for (int ni = 0; ni < 4; ni++) {
            int gn = ncol0 + ni * 8;
            if (gn < NENT) {
                int gm = mrow0 + mi * 16;
                float2 v0, v1;
                v0.x = sigmoidf_fast(acc[mi][ni][0]);
                v0.y = sigmoidf_fast(acc[mi][ni][1]);
                v1.x = sigmoidf_fast(acc[mi][ni][2]);
                v1.y = sigmoidf_fast(acc[mi][ni][3]);
                *(float2*)(out + (size_t)gm * NENT + gn) = v0;
                *(float2*)(out + (size_t)(gm + 8) * NENT + gn) = v1;
            }
        }
    }
}

// ---------------- launch ----------------
extern "C" void kernel_launch(void* const* d_in, const int* in_sizes, int n_in,
                              void* d_out, int out_size) {
    const float* E  = (const float*)d_in[0];
    const float* R1 = (const float*)d_in[1];
    const float* R2 = (const float*)d_in[2];
    const float* R3 = (const float*)d_in[3];
    const float* W1 = (const float*)d_in[4];
    const float* W2 = (const float*)d_in[5];
    const float* W3 = (const float*)d_in[6];
    const float* g0 = (const float*)d_in[7];
    const float* b0 = (const float*)d_in[8];
    const float* g1 = (const float*)d_in[9];
    const float* b1 = (const float*)d_in[10];
    const int* e1_idx = (const int*)d_in[11];
    const int* r_idx  = (const int*)d_in[12];
    float* out = (float*)d_out;

    cudaFuncSetAttribute(gemm_mma_kernel, cudaFuncAttributeMaxDynamicSharedMemorySize,
                         SMEM_GEMM);

    convert_E_kernel<<<NENT_PAD, 256>>>(E);
    zero_stats_kernel<<<4, 256>>>();
    bn0_stats_kernel<<<BATCHN / 8, 256>>>(E, e1_idx);
    build_M_kernel<<<dim3((D1 * D1 + 255) / 256, NRELS), 256>>>(R1, R2, R3, W1, W2, W3);
    mid_kernel<<<BATCHN, 256>>>(E, e1_idx, r_idx, g0, b0);
    x2_kernel<<<(BATCHN * D1 + 255) / 256, 256>>>(g1, b1);
    convert_A_kernel<<<BATCHN, 256>>>();
    gemm_mma_kernel<<<dim3(NTILES, MTILES), 256, SMEM_GEMM>>>(out);
}

// round 10
// speedup vs baseline: 1.7992x; 1.0902x over previous
#include <cuda_runtime.h>
#include <cuda_bf16.h>
#include <cstdint>

#define D1 200
#define NRELS 11
#define BATCHN 1024
#define NENT 100000
#define NENT_PAD 100096         // 782 * 128
#define KPAD 208                // 13 k16 steps
#define KSTEPS 13
#define NTILES 782
#define MTILES 8
#define ROWB 416                // KPAD * 2 bytes per gmem row

// ---------------- scratch (device globals; no allocation allowed) ----------------
__device__ __align__(16) float d_M[NRELS * D1 * D1];
__device__ __align__(16) float d_y[BATCHN * D1];
__device__ float d_stats[4 * D1];

__device__ __align__(16) __nv_bfloat16 d_Ahi[BATCHN * KPAD];
__device__ __align__(16) __nv_bfloat16 d_Alo[BATCHN * KPAD];
__device__ __align__(16) __nv_bfloat16 d_Ehi[(size_t)NENT_PAD * KPAD];
__device__ __align__(16) __nv_bfloat16 d_Elo[(size_t)NENT_PAD * KPAD];

// ---------------- PTX helpers (generic-PTX-safe) ----------------
__device__ __forceinline__ uint32_t smem_u32(const void* p) {
    uint32_t a;
    asm("{ .reg .u64 t; cvta.to.shared.u64 t, %1; cvt.u32.u64 %0, t; }" : "=r"(a) : "l"(p));
    return a;
}
__device__ __forceinline__ void cp16(uint32_t dst, const void* src) {
    asm volatile("cp.async.cg.shared.global [%0], [%1], 16;" :: "r"(dst), "l"(src) : "memory");
}
__device__ __forceinline__ void cp_commit() { asm volatile("cp.async.commit_group;" ::: "memory"); }
template <int N>
__device__ __forceinline__ void cp_wait() { asm volatile("cp.async.wait_group %0;" :: "n"(N) : "memory"); }

__device__ __forceinline__ void ldx4(uint32_t& r0, uint32_t& r1, uint32_t& r2, uint32_t& r3,
                                     uint32_t addr) {
    asm volatile("ldmatrix.sync.aligned.m8n8.x4.shared.b16 {%0,%1,%2,%3}, [%4];"
                 : "=r"(r0), "=r"(r1), "=r"(r2), "=r"(r3) : "r"(addr));
}
__device__ __forceinline__ void mma16816(float* c, const uint32_t* a, const uint32_t* b) {
    asm volatile(
        "mma.sync.aligned.m16n8k16.row.col.f32.bf16.bf16.f32 "
        "{%0,%1,%2,%3}, {%4,%5,%6,%7}, {%8,%9}, {%0,%1,%2,%3};"
        : "+f"(c[0]), "+f"(c[1]), "+f"(c[2]), "+f"(c[3])
        : "r"(a[0]), "r"(a[1]), "r"(a[2]), "r"(a[3]), "r"(b[0]), "r"(b[1]));
}

// ---------------- launch 1: convert E (float4) + zero stats ----------------
__global__ void convert_E_kernel(const float* __restrict__ E) {
    if (blockIdx.x == 0) {
        for (int t = threadIdx.x; t < 4 * D1; t += 256) d_stats[t] = 0.f;
    }
    int f4 = blockIdx.x * blockDim.x + threadIdx.x;   // 5,000,000 float4s
    if (f4 >= (NENT * D1) / 4) return;
    int row = f4 / 50;                 // 50 float4 per row (200/4)
    int col = (f4 - row * 50) * 4;
    float4 v = *(const float4*)(E + (size_t)f4 * 4);
    float fv[4] = {v.x, v.y, v.z, v.w};
    __nv_bfloat16 hi[4], lo[4];
#pragma unroll
    for (int i = 0; i < 4; i++) {
        hi[i] = __float2bfloat16(fv[i]);
        lo[i] = __float2bfloat16(fv[i] - __bfloat162float(hi[i]));
    }
    size_t o = (size_t)row * KPAD + col;
    *(__nv_bfloat162*)(d_Ehi + o)     = __nv_bfloat162(hi[0], hi[1]);
    *(__nv_bfloat162*)(d_Ehi + o + 2) = __nv_bfloat162(hi[2], hi[3]);
    *(__nv_bfloat162*)(d_Elo + o)     = __nv_bfloat162(lo[0], lo[1]);
    *(__nv_bfloat162*)(d_Elo + o + 2) = __nv_bfloat162(lo[2], lo[3]);
    // pad cols [200,208) and rows [100000,100096) stay zero from module init
}

// ---------------- launch 2: BN0 stats ----------------
__global__ void bn0_stats_kernel(const float* __restrict__ E, const int* __restrict__ e1_idx) {
    int j = threadIdx.x;
    if (j >= D1) return;
    float s = 0.f, ss = 0.f;
    int r0 = blockIdx.x * 8;
#pragma unroll
    for (int r = 0; r < 8; r++) {
        int e1 = e1_idx[r0 + r];
        float v = E[e1 * D1 + j];
        s += v; ss += v * v;
    }
    atomicAdd(&d_stats[j], s);
    atomicAdd(&d_stats[D1 + j], ss);
}

// ---------------- launch 3: build all 11 relation matrices, W loaded once ----------------
__global__ void build_M_kernel(const float* __restrict__ R1, const float* __restrict__ R2,
                               const float* __restrict__ R3, const float* __restrict__ W1,
                               const float* __restrict__ W2, const float* __restrict__ W3) {
    int e = blockIdx.x * blockDim.x + threadIdx.x;
    if (e >= D1 * D1) return;
    int j = e / D1, k = e % D1;
    int a = j < k ? j : k;
    int b = j < k ? k : j;
    int sidx = a * (2 * D1 - a + 1) / 2 + (b - a);
    float asign = 0.f; int aoff = 0;
    if (j < k)      { asign =  1.f; aoff = (2 * D1 - j - 1) * j / 2 + (k - j) - 1; }
    else if (j > k) { asign = -1.f; aoff = (2 * D1 - k - 1) * k / 2 + (j - k) - 1; }

    float m[NRELS];
#pragma unroll
    for (int r = 0; r < NRELS; r++) m[r] = 0.f;

#pragma unroll 5
    for (int s = 0; s < 30; s++) {
        float w1 = __ldg(W1 + s * 20100 + sidx);
        m[1]  = fmaf(__ldg(R1 + s),        w1, m[1]);
        m[8]  = fmaf(__ldg(R1 + 30 + s),   w1, m[8]);
        m[10] = fmaf(__ldg(R1 + 60 + s),   w1, m[10]);
        m[0]  = fmaf(__ldg(R3 + s),        w1, m[0]);
        m[3]  = fmaf(__ldg(R3 + 80 + s),   w1, m[3]);
        m[9]  = fmaf(__ldg(R3 + 160 + s),  w1, m[9]);
    }
    if (asign != 0.f) {
#pragma unroll 5
        for (int s = 0; s < 30; s++) {
            float w2 = asign * __ldg(W2 + s * 19900 + aoff);
            m[2] = fmaf(__ldg(R2 + s),        w2, m[2]);
            m[4] = fmaf(__ldg(R2 + 30 + s),   w2, m[4]);
            m[5] = fmaf(__ldg(R2 + 60 + s),   w2, m[5]);
            m[6] = fmaf(__ldg(R2 + 90 + s),   w2, m[6]);
            m[7] = fmaf(__ldg(R2 + 120 + s),  w2, m[7]);
            m[0] = fmaf(__ldg(R3 + 30 + s),   w2, m[0]);
            m[3] = fmaf(__ldg(R3 + 110 + s),  w2, m[3]);
            m[9] = fmaf(__ldg(R3 + 190 + s),  w2, m[9]);
        }
    }
#pragma unroll 5
    for (int o = 0; o < 20; o++) {
        float w3 = __ldg(W3 + o * 40000 + e);
        m[0] = fmaf(__ldg(R3 + 60 + o),   w3, m[0]);
        m[3] = fmaf(__ldg(R3 + 140 + o),  w3, m[3]);
        m[9] = fmaf(__ldg(R3 + 220 + o),  w3, m[9]);
    }
#pragma unroll
    for (int r = 0; r < NRELS; r++) d_M[r * 40000 + e] = m[r];
}

// ---------------- launch 4: y = M[r]^T bn0(E[e1]); BN1 stats ----------------
__global__ void mid_kernel(const float* __restrict__ E, const int* __restrict__ e1_idx,
                           const int* __restrict__ r_idx,
                           const float* __restrict__ g0, const float* __restrict__ b0) {
    __shared__ float xs[D1];
    int b = blockIdx.x;
    int t = threadIdx.x;
    if (t < D1) {
        float mean = d_stats[t] * (1.f / BATCHN);
        float var  = d_stats[D1 + t] * (1.f / BATCHN) - mean * mean;
        float inv  = rsqrtf(var + 1e-5f);
        int e1 = e1_idx[b];
        xs[t] = (E[e1 * D1 + t] - mean) * inv * g0[t] + b0[t];
    }
    __syncthreads();
    if (t < D1) {
        const float* M = d_M + r_idx[b] * 40000;
        float acc = 0.f;
#pragma unroll 8
        for (int jj = 0; jj < D1; jj++) acc += M[jj * D1 + t] * xs[jj];
        d_y[b * D1 + t] = acc;
        atomicAdd(&d_stats[2 * D1 + t], acc);
        atomicAdd(&d_stats[3 * D1 + t], acc * acc);
    }
}

// ---------------- launch 5: BN1 + split-convert A ----------------
__global__ void bn1_convA_kernel(const float* __restrict__ g1, const float* __restrict__ b1) {
    int row = blockIdx.x;
    int col = threadIdx.x;
    if (col >= D1) return;
    float mean = d_stats[2 * D1 + col] * (1.f / BATCHN);
    float var  = d_stats[3 * D1 + col] * (1.f / BATCHN) - mean * mean;
    float inv  = rsqrtf(var + 1e-5f);
    float v = (d_y[row * D1 + col] - mean) * inv * g1[col] + b1[col];
    __nv_bfloat16 h = __float2bfloat16(v);
    d_Ahi[row * KPAD + col] = h;
    d_Alo[row * KPAD + col] = __float2bfloat16(v - __bfloat162float(h));
    // pad cols stay zero from module init
}

// ---------------- sigmoid: 1 MUFU (EX2) + FMA-Newton reciprocal ----------------
__device__ __forceinline__ float sigmoidf_fast(float x) {
    x = fminf(fmaxf(x, -30.f), 30.f);
    float w = 1.0f + __expf(-x);                 // in [1, 1+e^30]
    float y = __int_as_float(0x7EF311C3 - __float_as_int(w));
    float e;
    e = fmaf(-w, y, 1.0f); y = fmaf(y, e, y);
    e = fmaf(-w, y, 1.0f); y = fmaf(y, e, y);
    e = fmaf(-w, y, 1.0f); y = fmaf(y, e, y);
    return y;
}

// ---------------- launch 6: bf16-split mma.sync GEMM + sigmoid ----------------
// CTA 128x128, 512 threads / 16 warps (4m x 4n), warp tile 32x32, K = 13 x k16.
// smem per stage: Ah/Al/Bh/Bl, each 128 rows x 48B (32B data + 16B pad) = 6144B.
#define NSTAGE 4
#define MAT_B  6144
#define STAGE_B (4 * MAT_B)          // 24576
#define SMEM_GEMM (NSTAGE * STAGE_B) // 98304

__global__ __launch_bounds__(512, 1)
void gemm_mma_kernel(float* __restrict__ out) {
    extern __shared__ __align__(128) char smem[];
    const uint32_t sb = smem_u32(smem);
    const int tid  = threadIdx.x;
    const int lane = tid & 31;
    const int wid  = tid >> 5;
    const int wm   = wid >> 2;       // 0..3  (32 rows each)
    const int wn   = wid & 3;        // 0..3  (32 cols each)

    const int m0 = blockIdx.y << 7;
    const int n0 = blockIdx.x << 7;

    // ---- cp.async mapping: 4 thread groups of 128 -> one matrix each, 2 x 16B ----
    const int mt = tid >> 7;         // 0:Ah 1:Al 2:Bh 3:Bl
    const int c0 = tid & 127;
    const char* gbase;
    {
        const char* gAh = (const char*)d_Ahi + (size_t)m0 * ROWB;
        const char* gAl = (const char*)d_Alo + (size_t)m0 * ROWB;
        const char* gBh = (const char*)d_Ehi + (size_t)n0 * ROWB;
        const char* gBl = (const char*)d_Elo + (size_t)n0 * ROWB;
        gbase = (mt == 0) ? gAh : (mt == 1) ? gAl : (mt == 2) ? gBh : gBl;
    }
    const uint32_t smat = sb + mt * MAT_B;

    auto issue = [&](int step, int slot) {
#pragma unroll
        for (int i = 0; i < 2; i++) {
            int c = c0 + 128 * i;
            int row = c >> 1, half = c & 1;
            cp16(smat + slot * STAGE_B + row * 48 + half * 16,
                 gbase + (size_t)row * ROWB + step * 32 + half * 16);
        }
        cp_commit();
    };

    // ---- ldmatrix per-lane offsets (48B rows -> conflict-free) ----
    const int g  = lane >> 3;
    const int l8 = lane & 7;
    // A x4 groups: (m0-7,k0),(m8-15,k0),(m0-7,k8),(m8-15,k8)
    const uint32_t a_off = (uint32_t)((wm * 32 + (g & 1) * 8 + l8) * 48 + (g >> 1) * 16);
    // B x4 groups: (n0-7,k0),(n0-7,k8),(n8-15,k0),(n8-15,k8)
    const uint32_t b_off = (uint32_t)(2 * MAT_B + (wn * 32 + (g >> 1) * 8 + l8) * 48 + (g & 1) * 16);

    float acc[2][4][4];
#pragma unroll
    for (int mi = 0; mi < 2; mi++)
#pragma unroll
        for (int ni = 0; ni < 4; ni++)
#pragma unroll
            for (int r = 0; r < 4; r++) acc[mi][ni][r] = 0.f;

    uint32_t ah[2][4], al[2][4], bh[4][2], bl[4][2];

    auto load_frags = [&](int slot) {
        uint32_t base = sb + slot * STAGE_B;
#pragma unroll
        for (int mi = 0; mi < 2; mi++) {
            ldx4(ah[mi][0], ah[mi][1], ah[mi][2], ah[mi][3], base + a_off + mi * 768);
            ldx4(al[mi][0], al[mi][1], al[mi][2], al[mi][3], base + MAT_B + a_off + mi * 768);
        }
#pragma unroll
        for (int p = 0; p < 2; p++) {
            ldx4(bh[2*p][0], bh[2*p][1], bh[2*p+1][0], bh[2*p+1][1], base + b_off + p * 768);
            ldx4(bl[2*p][0], bl[2*p][1], bl[2*p+1][0], bl[2*p+1][1],
                 base + MAT_B + b_off + p * 768);
        }
    };

    auto do_mma = [&]() {
#pragma unroll
        for (int mi = 0; mi < 2; mi++)
#pragma unroll
            for (int ni = 0; ni < 4; ni++) {
                mma16816(acc[mi][ni], ah[mi], bh[ni]);
                mma16816(acc[mi][ni], ah[mi], bl[ni]);
                mma16816(acc[mi][ni], al[mi], bh[ni]);
            }
    };

    // ---- pipeline: prologue 3 stages, steady wait<2>, peeled tail ----
    issue(0, 0); issue(1, 1); issue(2, 2);

    for (int i = 0; i < 11; i++) {
        cp_wait<2>();
        __syncthreads();
        load_frags(i & 3);
        if (i < 10) issue(i + 3, (i + 3) & 3);
        do_mma();
    }
    cp_wait<1>(); __syncthreads(); load_frags(11 & 3); do_mma();
    cp_wait<0>(); __syncthreads(); load_frags(12 & 3); do_mma();

    // ---- epilogue: sigmoid + float2 stores ----
    const int mrow0 = m0 + wm * 32 + (lane >> 2);
    const int ncol0 = n0 + wn * 32 + ((lane & 3) << 1);
#pragma unroll
    for (int mi = 0; mi < 2; mi++) {
#pragma unroll
        for (int ni = 0; ni < 4; ni++) {
            int gn = ncol0 + ni * 8;
            if (gn < NENT) {
                int gm = mrow0 + mi * 16;
                float2 v0, v1;
                v0.x = sigmoidf_fast(acc[mi][ni][0]);
                v0.y = sigmoidf_fast(acc[mi][ni][1]);
                v1.x = sigmoidf_fast(acc[mi][ni][2]);
                v1.y = sigmoidf_fast(acc[mi][ni][3]);
                *(float2*)(out + (size_t)gm * NENT + gn) = v0;
                *(float2*)(out + (size_t)(gm + 8) * NENT + gn) = v1;
            }
        }
    }
}

// ---------------- launch ----------------
extern "C" void kernel_launch(void* const* d_in, const int* in_sizes, int n_in,
                              void* d_out, int out_size) {
    const float* E  = (const float*)d_in[0];
    const float* R1 = (const float*)d_in[1];
    const float* R2 = (const float*)d_in[2];
    const float* R3 = (const float*)d_in[3];
    const float* W1 = (const float*)d_in[4];
    const float* W2 = (const float*)d_in[5];
    const float* W3 = (const float*)d_in[6];
    const float* g0 = (const float*)d_in[7];
    const float* b0 = (const float*)d_in[8];
    const float* g1 = (const float*)d_in[9];
    const float* b1 = (const float*)d_in[10];
    const int* e1_idx = (const int*)d_in[11];
    const int* r_idx  = (const int*)d_in[12];
    float* out = (float*)d_out;

    cudaFuncSetAttribute(gemm_mma_kernel, cudaFuncAttributeMaxDynamicSharedMemorySize,
                         SMEM_GEMM);

    convert_E_kernel<<<(NENT * D1 / 4 + 255) / 256, 256>>>(E);                 // 1
    bn0_stats_kernel<<<BATCHN / 8, 256>>>(E, e1_idx);                          // 2
    build_M_kernel<<<(D1 * D1 + 255) / 256, 256>>>(R1, R2, R3, W1, W2, W3);    // 3
    mid_kernel<<<BATCHN, 256>>>(E, e1_idx, r_idx, g0, b0);                     // 4
    bn1_convA_kernel<<<BATCHN, 256>>>(g1, b1);                                 // 5
    gemm_mma_kernel<<<dim3(NTILES, MTILES), 512, SMEM_GEMM>>>(out);            // 6
}

// round 11
// speedup vs baseline: 2.9364x; 1.6321x over previous
#include <cuda_runtime.h>
#include <cuda_fp16.h>
#include <cstdint>

#define D1 200
#define NRELS 11
#define BATCHN 1024
#define NENT 100000
#define NENT_PAD 100096         // 782 * 128
#define KPAD 208                // 13 k16 steps
#define KSTEPS 13
#define NTILES 782
#define MTILES 8
#define ROWB 416                // KPAD * 2 bytes per gmem row

// ---------------- scratch (device globals; no allocation allowed) ----------------
__device__ __align__(16) float d_M[NRELS * D1 * D1];
__device__ __align__(16) float d_y[BATCHN * D1];
__device__ float d_stats[2 * D1];                  // BN1 sum / sumsq (atomics)
__device__ float d_bn0p[2 * 32 * D1];              // BN0 partials: 32 blocks x (sum|sumsq)

__device__ __align__(16) __half d_Af16[BATCHN * KPAD];
__device__ __align__(16) __half d_Ef16[(size_t)NENT_PAD * KPAD];

// ---------------- PTX helpers (generic-PTX-safe) ----------------
__device__ __forceinline__ uint32_t smem_u32(const void* p) {
    uint32_t a;
    asm("{ .reg .u64 t; cvta.to.shared.u64 t, %1; cvt.u32.u64 %0, t; }" : "=r"(a) : "l"(p));
    return a;
}
__device__ __forceinline__ void cp16(uint32_t dst, const void* src) {
    asm volatile("cp.async.cg.shared.global [%0], [%1], 16;" :: "r"(dst), "l"(src) : "memory");
}
__device__ __forceinline__ void cp_commit() { asm volatile("cp.async.commit_group;" ::: "memory"); }
template <int N>
__device__ __forceinline__ void cp_wait() { asm volatile("cp.async.wait_group %0;" :: "n"(N) : "memory"); }

__device__ __forceinline__ void ldx4(uint32_t& r0, uint32_t& r1, uint32_t& r2, uint32_t& r3,
                                     uint32_t addr) {
    asm volatile("ldmatrix.sync.aligned.m8n8.x4.shared.b16 {%0,%1,%2,%3}, [%4];"
                 : "=r"(r0), "=r"(r1), "=r"(r2), "=r"(r3) : "r"(addr));
}
__device__ __forceinline__ void mma16816h(float* c, const uint32_t* a, const uint32_t* b) {
    asm volatile(
        "mma.sync.aligned.m16n8k16.row.col.f32.f16.f16.f32 "
        "{%0,%1,%2,%3}, {%4,%5,%6,%7}, {%8,%9}, {%0,%1,%2,%3};"
        : "+f"(c[0]), "+f"(c[1]), "+f"(c[2]), "+f"(c[3])
        : "r"(a[0]), "r"(a[1]), "r"(a[2]), "r"(a[3]), "r"(b[0]), "r"(b[1]));
}

// ---------------- launch 1: mega-prep (independent block ranges) ----------------
// [0, NB_CONV)            : convert E -> fp16 (float4 granularity)
// [NB_CONV, +NB_BN0)      : BN0 partial sums (no atomics)
// [.., +NB_BM)            : build all 11 relation matrices (W loaded once)
// last block              : zero BN1 stat slots
#define NB_CONV 19532           // ceil(5,000,000 / 256)
#define NB_BN0  32
#define NB_BM   157             // ceil(40000 / 256)
#define NB_PREP (NB_CONV + NB_BN0 + NB_BM + 1)

__global__ void prep_kernel(const float* __restrict__ E, const int* __restrict__ e1_idx,
                            const float* __restrict__ R1, const float* __restrict__ R2,
                            const float* __restrict__ R3, const float* __restrict__ W1,
                            const float* __restrict__ W2, const float* __restrict__ W3) {
    const int bid = blockIdx.x;
    const int tid = threadIdx.x;

    if (bid < NB_CONV) {
        int f4 = bid * 256 + tid;                   // 5,000,000 float4s
        if (f4 >= (NENT * D1) / 4) return;
        int row = f4 / 50;                          // 50 float4 per row
        int col = (f4 - row * 50) * 4;
        float4 v = *(const float4*)(E + (size_t)f4 * 4);
        __half2 h01 = __floats2half2_rn(v.x, v.y);
        __half2 h23 = __floats2half2_rn(v.z, v.w);
        size_t o = (size_t)row * KPAD + col;
        *(__half2*)(d_Ef16 + o)     = h01;
        *(__half2*)(d_Ef16 + o + 2) = h23;
        // pad cols [200,208) and rows [100000,100096) stay zero from module init
        return;
    }
    if (bid < NB_CONV + NB_BN0) {
        int b2 = bid - NB_CONV;                     // 0..31, covers 32 batch rows
        int j = tid;
        if (j >= D1) return;
        float s = 0.f, ss = 0.f;
#pragma unroll 8
        for (int r = 0; r < 32; r++) {
            int e1 = e1_idx[b2 * 32 + r];
            float v = E[e1 * D1 + j];
            s += v; ss += v * v;
        }
        d_bn0p[b2 * D1 + j] = s;
        d_bn0p[32 * D1 + b2 * D1 + j] = ss;
        return;
    }
    if (bid < NB_CONV + NB_BN0 + NB_BM) {
        int e = (bid - NB_CONV - NB_BN0) * 256 + tid;
        if (e >= D1 * D1) return;
        int j = e / D1, k = e % D1;
        int a = j < k ? j : k;
        int b = j < k ? k : j;
        int sidx = a * (2 * D1 - a + 1) / 2 + (b - a);
        float asign = 0.f; int aoff = 0;
        if (j < k)      { asign =  1.f; aoff = (2 * D1 - j - 1) * j / 2 + (k - j) - 1; }
        else if (j > k) { asign = -1.f; aoff = (2 * D1 - k - 1) * k / 2 + (j - k) - 1; }

        float m[NRELS];
#pragma unroll
        for (int r = 0; r < NRELS; r++) m[r] = 0.f;

#pragma unroll 5
        for (int s = 0; s < 30; s++) {
            float w1 = __ldg(W1 + s * 20100 + sidx);
            m[1]  = fmaf(__ldg(R1 + s),        w1, m[1]);
            m[8]  = fmaf(__ldg(R1 + 30 + s),   w1, m[8]);
            m[10] = fmaf(__ldg(R1 + 60 + s),   w1, m[10]);
            m[0]  = fmaf(__ldg(R3 + s),        w1, m[0]);
            m[3]  = fmaf(__ldg(R3 + 80 + s),   w1, m[3]);
            m[9]  = fmaf(__ldg(R3 + 160 + s),  w1, m[9]);
        }
        if (asign != 0.f) {
#pragma unroll 5
            for (int s = 0; s < 30; s++) {
                float w2 = asign * __ldg(W2 + s * 19900 + aoff);
                m[2] = fmaf(__ldg(R2 + s),        w2, m[2]);
                m[4] = fmaf(__ldg(R2 + 30 + s),   w2, m[4]);
                m[5] = fmaf(__ldg(R2 + 60 + s),   w2, m[5]);
                m[6] = fmaf(__ldg(R2 + 90 + s),   w2, m[6]);
                m[7] = fmaf(__ldg(R2 + 120 + s),  w2, m[7]);
                m[0] = fmaf(__ldg(R3 + 30 + s),   w2, m[0]);
                m[3] = fmaf(__ldg(R3 + 110 + s),  w2, m[3]);
                m[9] = fmaf(__ldg(R3 + 190 + s),  w2, m[9]);
            }
        }
#pragma unroll 5
        for (int o = 0; o < 20; o++) {
            float w3 = __ldg(W3 + o * 40000 + e);
            m[0] = fmaf(__ldg(R3 + 60 + o),   w3, m[0]);
            m[3] = fmaf(__ldg(R3 + 140 + o),  w3, m[3]);
            m[9] = fmaf(__ldg(R3 + 220 + o),  w3, m[9]);
        }
#pragma unroll
        for (int r = 0; r < NRELS; r++) d_M[r * 40000 + e] = m[r];
        return;
    }
    // last block: zero BN1 stat slots
    for (int t = tid; t < 2 * D1; t += 256) d_stats[t] = 0.f;
}

// ---------------- launch 2: y = M[r]^T bn0(E[e1]); BN1 atomics ----------------
__global__ void mid_kernel(const float* __restrict__ E, const int* __restrict__ e1_idx,
                           const int* __restrict__ r_idx,
                           const float* __restrict__ g0, const float* __restrict__ b0) {
    __shared__ float xs[D1];
    int b = blockIdx.x;
    int t = threadIdx.x;
    if (t < D1) {
        float s = 0.f, ss = 0.f;
#pragma unroll 8
        for (int i = 0; i < 32; i++) {
            s  += d_bn0p[i * D1 + t];
            ss += d_bn0p[32 * D1 + i * D1 + t];
        }
        float mean = s * (1.f / BATCHN);
        float var  = ss * (1.f / BATCHN) - mean * mean;
        float inv  = rsqrtf(var + 1e-5f);
        int e1 = e1_idx[b];
        xs[t] = (E[e1 * D1 + t] - mean) * inv * g0[t] + b0[t];
    }
    __syncthreads();
    if (t < D1) {
        const float* M = d_M + r_idx[b] * 40000;
        float acc = 0.f;
#pragma unroll 8
        for (int jj = 0; jj < D1; jj++) acc += M[jj * D1 + t] * xs[jj];
        d_y[b * D1 + t] = acc;
        atomicAdd(&d_stats[t], acc);
        atomicAdd(&d_stats[D1 + t], acc * acc);
    }
}

// ---------------- launch 3: BN1 + fp16 convert A ----------------
__global__ void bn1_convA_kernel(const float* __restrict__ g1, const float* __restrict__ b1) {
    int row = blockIdx.x;
    int col = threadIdx.x;
    if (col >= D1) return;
    float mean = d_stats[col] * (1.f / BATCHN);
    float var  = d_stats[D1 + col] * (1.f / BATCHN) - mean * mean;
    float inv  = rsqrtf(var + 1e-5f);
    float v = (d_y[row * D1 + col] - mean) * inv * g1[col] + b1[col];
    d_Af16[row * KPAD + col] = __float2half_rn(v);
    // pad cols stay zero from module init
}

// ---------------- sigmoid: 1 MUFU (EX2) + FMA-Newton reciprocal ----------------
__device__ __forceinline__ float sigmoidf_fast(float x) {
    x = fminf(fmaxf(x, -30.f), 30.f);
    float w = 1.0f + __expf(-x);
    float y = __int_as_float(0x7EF311C3 - __float_as_int(w));
    float e;
    e = fmaf(-w, y, 1.0f); y = fmaf(y, e, y);
    e = fmaf(-w, y, 1.0f); y = fmaf(y, e, y);
    e = fmaf(-w, y, 1.0f); y = fmaf(y, e, y);
    return y;
}

// ---------------- launch 4: single-term fp16 mma GEMM + sigmoid ----------------
// CTA 128x128, 512 threads / 16 warps (4m x 4n), warp tile 32x32, K = 13 x k16.
// smem per stage: A + B, each 128 rows x 48B (32B data + 16B pad) = 6144B.
#define NSTAGE 4
#define MAT_B  6144
#define STAGE_B (2 * MAT_B)          // 12288
#define SMEM_GEMM (NSTAGE * STAGE_B) // 49152

__global__ __launch_bounds__(512, 1)
void gemm_mma_kernel(float* __restrict__ out) {
    extern __shared__ __align__(128) char smem[];
    const uint32_t sb = smem_u32(smem);
    const int tid  = threadIdx.x;
    const int lane = tid & 31;
    const int wid  = tid >> 5;
    const int wm   = wid >> 2;       // 0..3  (32 rows each)
    const int wn   = wid & 3;        // 0..3  (32 cols each)

    const int m0 = blockIdx.y << 7;
    const int n0 = blockIdx.x << 7;

    // ---- cp.async: 2 groups of 256 threads -> one matrix each, 1 x 16B per thread ----
    const int mt = tid >> 8;         // 0:A 1:B
    const int c0 = tid & 255;
    const char* gbase = (mt == 0)
        ? (const char*)d_Af16 + (size_t)m0 * ROWB
        : (const char*)d_Ef16 + (size_t)n0 * ROWB;
    const uint32_t smat = sb + mt * MAT_B;
    const int lrow = c0 >> 1, lhalf = c0 & 1;

    auto issue = [&](int step, int slot) {
        cp16(smat + slot * STAGE_B + lrow * 48 + lhalf * 16,
             gbase + (size_t)lrow * ROWB + step * 32 + lhalf * 16);
        cp_commit();
    };

    // ---- ldmatrix per-lane offsets (48B rows -> conflict-free) ----
    const int g  = lane >> 3;
    const int l8 = lane & 7;
    // A x4 groups: (m0-7,k0),(m8-15,k0),(m0-7,k8),(m8-15,k8)
    const uint32_t a_off = (uint32_t)((wm * 32 + (g & 1) * 8 + l8) * 48 + (g >> 1) * 16);
    // B x4 groups: (n0-7,k0),(n0-7,k8),(n8-15,k0),(n8-15,k8)
    const uint32_t b_off = (uint32_t)(MAT_B + (wn * 32 + (g >> 1) * 8 + l8) * 48 + (g & 1) * 16);

    float acc[2][4][4];
#pragma unroll
    for (int mi = 0; mi < 2; mi++)
#pragma unroll
        for (int ni = 0; ni < 4; ni++)
#pragma unroll
            for (int r = 0; r < 4; r++) acc[mi][ni][r] = 0.f;

    uint32_t ah[2][4], bh[4][2];

    auto load_frags = [&](int slot) {
        uint32_t base = sb + slot * STAGE_B;
#pragma unroll
        for (int mi = 0; mi < 2; mi++)
            ldx4(ah[mi][0], ah[mi][1], ah[mi][2], ah[mi][3], base + a_off + mi * 768);
#pragma unroll
        for (int p = 0; p < 2; p++)
            ldx4(bh[2*p][0], bh[2*p][1], bh[2*p+1][0], bh[2*p+1][1], base + b_off + p * 768);
    };

    auto do_mma = [&]() {
#pragma unroll
        for (int mi = 0; mi < 2; mi++)
#pragma unroll
            for (int ni = 0; ni < 4; ni++)
                mma16816h(acc[mi][ni], ah[mi], bh[ni]);
    };

    // ---- pipeline: prologue 3 stages, steady wait<2>, peeled tail ----
    issue(0, 0); issue(1, 1); issue(2, 2);

    for (int i = 0; i < 11; i++) {
        cp_wait<2>();
        __syncthreads();
        load_frags(i & 3);
        if (i < 10) issue(i + 3, (i + 3) & 3);
        do_mma();
    }
    cp_wait<1>(); __syncthreads(); load_frags(11 & 3); do_mma();
    cp_wait<0>(); __syncthreads(); load_frags(12 & 3); do_mma();

    // ---- epilogue: sigmoid + float2 stores ----
    const int mrow0 = m0 + wm * 32 + (lane >> 2);
    const int ncol0 = n0 + wn * 32 + ((lane & 3) << 1);
#pragma unroll
    for (int mi = 0; mi < 2; mi++) {
#pragma unroll
        for (int ni = 0; ni < 4; ni++) {
            int gn = ncol0 + ni * 8;
            if (gn < NENT) {
                int gm = mrow0 + mi * 16;
                float2 v0, v1;
                v0.x = sigmoidf_fast(acc[mi][ni][0]);
                v0.y = sigmoidf_fast(acc[mi][ni][1]);
                v1.x = sigmoidf_fast(acc[mi][ni][2]);
                v1.y = sigmoidf_fast(acc[mi][ni][3]);
                *(float2*)(out + (size_t)gm * NENT + gn) = v0;
                *(float2*)(out + (size_t)(gm + 8) * NENT + gn) = v1;
            }
        }
    }
}

// ---------------- launch ----------------
extern "C" void kernel_launch(void* const* d_in, const int* in_sizes, int n_in,
                              void* d_out, int out_size) {
    const float* E  = (const float*)d_in[0];
    const float* R1 = (const float*)d_in[1];
    const float* R2 = (const float*)d_in[2];
    const float* R3 = (const float*)d_in[3];
    const float* W1 = (const float*)d_in[4];
    const float* W2 = (const float*)d_in[5];
    const float* W3 = (const float*)d_in[6];
    const float* g0 = (const float*)d_in[7];
    const float* b0 = (const float*)d_in[8];
    const float* g1 = (const float*)d_in[9];
    const float* b1 = (const float*)d_in[10];
    const int* e1_idx = (const int*)d_in[11];
    const int* r_idx  = (const int*)d_in[12];
    float* out = (float*)d_out;

    cudaFuncSetAttribute(gemm_mma_kernel, cudaFuncAttributeMaxDynamicSharedMemorySize,
                         SMEM_GEMM);

    prep_kernel<<<NB_PREP, 256>>>(E, e1_idx, R1, R2, R3, W1, W2, W3);   // 1
    mid_kernel<<<BATCHN, 256>>>(E, e1_idx, r_idx, g0, b0);              // 2
    bn1_convA_kernel<<<BATCHN, 256>>>(g1, b1);                          // 3
    gemm_mma_kernel<<<dim3(NTILES, MTILES), 512, SMEM_GEMM>>>(out);     // 4
}

// round 14
// speedup vs baseline: 3.3732x; 1.1487x over previous
#include <cuda_runtime.h>
#include <cuda_fp16.h>
#include <cstdint>

#define D1 200
#define NRELS 11
#define BATCHN 1024
#define NENT 100000
#define NENT_PAD 100096         // 782 * 128
#define KPAD 208                // 13 k16 steps
#define KSTEPS 13
#define NTILES 782
#define MTILES 8
#define ROWB 416                // KPAD * 2 bytes per gmem row

// ---------------- scratch (device globals; no allocation allowed) ----------------
__device__ __align__(16) float d_M[NRELS * D1 * D1];
__device__ __align__(16) float d_y[BATCHN * D1];
__device__ float d_stats[2 * D1];                  // BN1 sum / sumsq (atomics)
__device__ float d_bn0p[2 * 32 * D1];              // BN0 partials: 32 blocks x (sum|sumsq)

__device__ __align__(16) __half d_Af16[BATCHN * KPAD];
__device__ __align__(16) __half d_Ef16[(size_t)NENT_PAD * KPAD];

// ---------------- PTX helpers (generic-PTX-safe) ----------------
__device__ __forceinline__ uint32_t smem_u32(const void* p) {
    uint32_t a;
    asm("{ .reg .u64 t; cvta.to.shared.u64 t, %1; cvt.u32.u64 %0, t; }" : "=r"(a) : "l"(p));
    return a;
}
__device__ __forceinline__ void cp16(uint32_t dst, const void* src) {
    asm volatile("cp.async.cg.shared.global [%0], [%1], 16;" :: "r"(dst), "l"(src) : "memory");
}
__device__ __forceinline__ void cp_commit() { asm volatile("cp.async.commit_group;" ::: "memory"); }
template <int N>
__device__ __forceinline__ void cp_wait() { asm volatile("cp.async.wait_group %0;" :: "n"(N) : "memory"); }

__device__ __forceinline__ void ldx4(uint32_t& r0, uint32_t& r1, uint32_t& r2, uint32_t& r3,
                                     uint32_t addr) {
    asm volatile("ldmatrix.sync.aligned.m8n8.x4.shared.b16 {%0,%1,%2,%3}, [%4];"
                 : "=r"(r0), "=r"(r1), "=r"(r2), "=r"(r3) : "r"(addr));
}
__device__ __forceinline__ void mma16816h(float* c, const uint32_t* a, const uint32_t* b) {
    asm volatile(
        "mma.sync.aligned.m16n8k16.row.col.f32.f16.f16.f32 "
        "{%0,%1,%2,%3}, {%4,%5,%6,%7}, {%8,%9}, {%0,%1,%2,%3};"
        : "+f"(c[0]), "+f"(c[1]), "+f"(c[2]), "+f"(c[3])
        : "r"(a[0]), "r"(a[1]), "r"(a[2]), "r"(a[3]), "r"(b[0]), "r"(b[1]));
}

// ---------------- launch 1: mega-prep (independent block ranges) ----------------
#define NB_CONV 19532           // ceil(5,000,000 / 256)
#define NB_BN0  32
#define NB_BM   157             // ceil(40000 / 256)
#define NB_PREP (NB_CONV + NB_BN0 + NB_BM + 1)

__global__ void prep_kernel(const float* __restrict__ E, const int* __restrict__ e1_idx,
                            const float* __restrict__ R1, const float* __restrict__ R2,
                            const float* __restrict__ R3, const float* __restrict__ W1,
                            const float* __restrict__ W2, const float* __restrict__ W3) {
    const int bid = blockIdx.x;
    const int tid = threadIdx.x;

    if (bid < NB_CONV) {
        int f4 = bid * 256 + tid;                   // 5,000,000 float4s
        if (f4 >= (NENT * D1) / 4) return;
        int row = f4 / 50;                          // 50 float4 per row
        int col = (f4 - row * 50) * 4;
        float4 v = *(const float4*)(E + (size_t)f4 * 4);
        __half2 h01 = __floats2half2_rn(v.x, v.y);
        __half2 h23 = __floats2half2_rn(v.z, v.w);
        size_t o = (size_t)row * KPAD + col;
        *(__half2*)(d_Ef16 + o)     = h01;
        *(__half2*)(d_Ef16 + o + 2) = h23;
        return;
    }
    if (bid < NB_CONV + NB_BN0) {
        int b2 = bid - NB_CONV;                     // 0..31, covers 32 batch rows
        int j = tid;
        if (j >= D1) return;
        float s = 0.f, ss = 0.f;
#pragma unroll 8
        for (int r = 0; r < 32; r++) {
            int e1 = e1_idx[b2 * 32 + r];
            float v = E[e1 * D1 + j];
            s += v; ss += v * v;
        }
        d_bn0p[b2 * D1 + j] = s;
        d_bn0p[32 * D1 + b2 * D1 + j] = ss;
        return;
    }
    if (bid < NB_CONV + NB_BN0 + NB_BM) {
        int e = (bid - NB_CONV - NB_BN0) * 256 + tid;
        if (e >= D1 * D1) return;
        int j = e / D1, k = e % D1;
        int a = j < k ? j : k;
        int b = j < k ? k : j;
        int sidx = a * (2 * D1 - a + 1) / 2 + (b - a);
        float asign = 0.f; int aoff = 0;
        if (j < k)      { asign =  1.f; aoff = (2 * D1 - j - 1) * j / 2 + (k - j) - 1; }
        else if (j > k) { asign = -1.f; aoff = (2 * D1 - k - 1) * k / 2 + (j - k) - 1; }

        float m[NRELS];
#pragma unroll
        for (int r = 0; r < NRELS; r++) m[r] = 0.f;

#pragma unroll 5
        for (int s = 0; s < 30; s++) {
            float w1 = __ldg(W1 + s * 20100 + sidx);
            m[1]  = fmaf(__ldg(R1 + s),        w1, m[1]);
            m[8]  = fmaf(__ldg(R1 + 30 + s),   w1, m[8]);
            m[10] = fmaf(__ldg(R1 + 60 + s),   w1, m[10]);
            m[0]  = fmaf(__ldg(R3 + s),        w1, m[0]);
            m[3]  = fmaf(__ldg(R3 + 80 + s),   w1, m[3]);
            m[9]  = fmaf(__ldg(R3 + 160 + s),  w1, m[9]);
        }
        if (asign != 0.f) {
#pragma unroll 5
            for (int s = 0; s < 30; s++) {
                float w2 = asign * __ldg(W2 + s * 19900 + aoff);
                m[2] = fmaf(__ldg(R2 + s),        w2, m[2]);
                m[4] = fmaf(__ldg(R2 + 30 + s),   w2, m[4]);
                m[5] = fmaf(__ldg(R2 + 60 + s),   w2, m[5]);
                m[6] = fmaf(__ldg(R2 + 90 + s),   w2, m[6]);
                m[7] = fmaf(__ldg(R2 + 120 + s),  w2, m[7]);
                m[0] = fmaf(__ldg(R3 + 30 + s),   w2, m[0]);
                m[3] = fmaf(__ldg(R3 + 110 + s),  w2, m[3]);
                m[9] = fmaf(__ldg(R3 + 190 + s),  w2, m[9]);
            }
        }
#pragma unroll 5
        for (int o = 0; o < 20; o++) {
            float w3 = __ldg(W3 + o * 40000 + e);
            m[0] = fmaf(__ldg(R3 + 60 + o),   w3, m[0]);
            m[3] = fmaf(__ldg(R3 + 140 + o),  w3, m[3]);
            m[9] = fmaf(__ldg(R3 + 220 + o),  w3, m[9]);
        }
#pragma unroll
        for (int r = 0; r < NRELS; r++) d_M[r * 40000 + e] = m[r];
        return;
    }
    for (int t = tid; t < 2 * D1; t += 256) d_stats[t] = 0.f;
}

// ---------------- launch 2: y = M[r]^T bn0(E[e1]); BN1 atomics ----------------
__global__ void mid_kernel(const float* __restrict__ E, const int* __restrict__ e1_idx,
                           const int* __restrict__ r_idx,
                           const float* __restrict__ g0, const float* __restrict__ b0) {
    __shared__ float xs[D1];
    int b = blockIdx.x;
    int t = threadIdx.x;
    if (t < D1) {
        float s = 0.f, ss = 0.f;
#pragma unroll 8
        for (int i = 0; i < 32; i++) {
            s  += d_bn0p[i * D1 + t];
            ss += d_bn0p[32 * D1 + i * D1 + t];
        }
        float mean = s * (1.f / BATCHN);
        float var  = ss * (1.f / BATCHN) - mean * mean;
        float inv  = rsqrtf(var + 1e-5f);
        int e1 = e1_idx[b];
        xs[t] = (E[e1 * D1 + t] - mean) * inv * g0[t] + b0[t];
    }
    __syncthreads();
    if (t < D1) {
        const float* M = d_M + r_idx[b] * 40000;
        float acc = 0.f;
#pragma unroll 8
        for (int jj = 0; jj < D1; jj++) acc += M[jj * D1 + t] * xs[jj];
        d_y[b * D1 + t] = acc;
        atomicAdd(&d_stats[t], acc);
        atomicAdd(&d_stats[D1 + t], acc * acc);
    }
}

// ---------------- launch 3: BN1 + fp16 convert A ----------------
__global__ void bn1_convA_kernel(const float* __restrict__ g1, const float* __restrict__ b1) {
    int row = blockIdx.x;
    int col = threadIdx.x;
    if (col >= D1) return;
    float mean = d_stats[col] * (1.f / BATCHN);
    float var  = d_stats[D1 + col] * (1.f / BATCHN) - mean * mean;
    float inv  = rsqrtf(var + 1e-5f);
    float v = (d_y[row * D1 + col] - mean) * inv * g1[col] + b1[col];
    d_Af16[row * KPAD + col] = __float2half_rn(v);
}

// ---------------- sigmoid: 1 MUFU (EX2) + FMA-Newton reciprocal ----------------
__device__ __forceinline__ float sigmoidf_fast(float x) {
    x = fminf(fmaxf(x, -30.f), 30.f);
    float w = 1.0f + __expf(-x);
    float y = __int_as_float(0x7EF311C3 - __float_as_int(w));
    float e;
    e = fmaf(-w, y, 1.0f); y = fmaf(y, e, y);
    e = fmaf(-w, y, 1.0f); y = fmaf(y, e, y);
    e = fmaf(-w, y, 1.0f); y = fmaf(y, e, y);
    return y;
}

// ---------------- launch 4: single-term fp16 mma GEMM + sigmoid ----------------
// CTA 128x128, 512 threads / 16 warps (4m x 4n), warp tile 32x32, K = 13 x k16.
// __launch_bounds__(512, 2): force regs<=64 so 2 CTAs co-reside per SM (occupancy
// 25% -> ~50%), letting one CTA's MMAs cover the other's barriers/cp.async waits.
// smem per stage: A + B, each 128 rows x 48B (32B data + 16B pad) = 6144B.
#define NSTAGE 5
#define MAT_B  6144
#define STAGE_B (2 * MAT_B)          // 12288
#define SMEM_GEMM (NSTAGE * STAGE_B) // 61440 (x2 CTAs = 120KB < 228KB)

__global__ __launch_bounds__(512, 2)
void gemm_mma_kernel(float* __restrict__ out) {
    extern __shared__ __align__(128) char smem[];
    const uint32_t sb = smem_u32(smem);
    const int tid  = threadIdx.x;
    const int lane = tid & 31;
    const int wid  = tid >> 5;
    const int wm   = wid >> 2;       // 0..3  (32 rows each)
    const int wn   = wid & 3;        // 0..3  (32 cols each)

    const int m0 = blockIdx.y << 7;
    const int n0 = blockIdx.x << 7;

    // ---- cp.async: 2 groups of 256 threads -> one matrix each, 1 x 16B per thread ----
    const int mt = tid >> 8;         // 0:A 1:B
    const int c0 = tid & 255;
    const char* gbase = (mt == 0)
        ? (const char*)d_Af16 + (size_t)m0 * ROWB
        : (const char*)d_Ef16 + (size_t)n0 * ROWB;
    const uint32_t smat = sb + mt * MAT_B;
    const int lrow = c0 >> 1, lhalf = c0 & 1;

    auto issue = [&](int step, int slot) {
        cp16(smat + slot * STAGE_B + lrow * 48 + lhalf * 16,
             gbase + (size_t)lrow * ROWB + step * 32 + lhalf * 16);
        cp_commit();
    };

    // ---- ldmatrix per-lane offsets (48B rows -> conflict-free) ----
    const int g  = lane >> 3;
    const int l8 = lane & 7;
    const uint32_t a_off = (uint32_t)((wm * 32 + (g & 1) * 8 + l8) * 48 + (g >> 1) * 16);
    const uint32_t b_off = (uint32_t)(MAT_B + (wn * 32 + (g >> 1) * 8 + l8) * 48 + (g & 1) * 16);

    float acc[2][4][4];
#pragma unroll
    for (int mi = 0; mi < 2; mi++)
#pragma unroll
        for (int ni = 0; ni < 4; ni++)
#pragma unroll
            for (int r = 0; r < 4; r++) acc[mi][ni][r] = 0.f;

    uint32_t ah[2][4], bh[4][2];

    auto load_frags = [&](int slot) {
        uint32_t base = sb + slot * STAGE_B;
#pragma unroll
        for (int mi = 0; mi < 2; mi++)
            ldx4(ah[mi][0], ah[mi][1], ah[mi][2], ah[mi][3], base + a_off + mi * 768);
#pragma unroll
        for (int p = 0; p < 2; p++)
            ldx4(bh[2*p][0], bh[2*p][1], bh[2*p+1][0], bh[2*p+1][1], base + b_off + p * 768);
    };

    auto do_mma = [&]() {
#pragma unroll
        for (int mi = 0; mi < 2; mi++)
#pragma unroll
            for (int ni = 0; ni < 4; ni++)
                mma16816h(acc[mi][ni], ah[mi], bh[ni]);
    };

    // ---- pipeline: prologue 4 stages, steady wait<3>, peeled tail ----
    issue(0, 0); issue(1, 1); issue(2, 2); issue(3, 3);

    for (int i = 0; i < 10; i++) {
        cp_wait<3>();
        __syncthreads();
        load_frags(i % NSTAGE);
        if (i < 9) issue(i + 4, (i + 4) % NSTAGE);
        do_mma();
    }
    cp_wait<2>(); __syncthreads(); load_frags(10 % NSTAGE); do_mma();
    cp_wait<1>(); __syncthreads(); load_frags(11 % NSTAGE); do_mma();
    cp_wait<0>(); __syncthreads(); load_frags(12 % NSTAGE); do_mma();

    // ---- epilogue: sigmoid + float2 stores ----
    const int mrow0 = m0 + wm * 32 + (lane >> 2);
    const int ncol0 = n0 + wn * 32 + ((lane & 3) << 1);
#pragma unroll
    for (int mi = 0; mi < 2; mi++) {
#pragma unroll
        for (int ni = 0; ni < 4; ni++) {
            int gn = ncol0 + ni * 8;
            if (gn < NENT) {
                int gm = mrow0 + mi * 16;
                float2 v0, v1;
                v0.x = sigmoidf_fast(acc[mi][ni][0]);
                v0.y = sigmoidf_fast(acc[mi][ni][1]);
                v1.x = sigmoidf_fast(acc[mi][ni][2]);
                v1.y = sigmoidf_fast(acc[mi][ni][3]);
                *(float2*)(out + (size_t)gm * NENT + gn) = v0;
                *(float2*)(out + (size_t)(gm + 8) * NENT + gn) = v1;
            }
        }
    }
}

// ---------------- launch ----------------
extern "C" void kernel_launch(void* const* d_in, const int* in_sizes, int n_in,
                              void* d_out, int out_size) {
    const float* E  = (const float*)d_in[0];
    const float* R1 = (const float*)d_in[1];
    const float* R2 = (const float*)d_in[2];
    const float* R3 = (const float*)d_in[3];
    const float* W1 = (const float*)d_in[4];
    const float* W2 = (const float*)d_in[5];
    const float* W3 = (const float*)d_in[6];
    const float* g0 = (const float*)d_in[7];
    const float* b0 = (const float*)d_in[8];
    const float* g1 = (const float*)d_in[9];
    const float* b1 = (const float*)d_in[10];
    const int* e1_idx = (const int*)d_in[11];
    const int* r_idx  = (const int*)d_in[12];
    float* out = (float*)d_out;

    cudaFuncSetAttribute(gemm_mma_kernel, cudaFuncAttributeMaxDynamicSharedMemorySize,
                         SMEM_GEMM);

    prep_kernel<<<NB_PREP, 256>>>(E, e1_idx, R1, R2, R3, W1, W2, W3);   // 1
    mid_kernel<<<BATCHN, 256>>>(E, e1_idx, r_idx, g0, b0);              // 2
    bn1_convA_kernel<<<BATCHN, 256>>>(g1, b1);                          // 3
    gemm_mma_kernel<<<dim3(NTILES, MTILES), 512, SMEM_GEMM>>>(out);     // 4
}

// round 16
// speedup vs baseline: 3.3842x; 1.0033x over previous
#include <cuda_runtime.h>
#include <cuda_fp16.h>
#include <cstdint>

#define D1 200
#define NRELS 11
#define BATCHN 1024
#define NENT 100000
#define NENT_PAD 100096         // 782 * 128
#define KPAD 208                // 13 k16 steps
#define KSTEPS 13
#define NTILES 782
#define MTILES 8
#define ROWB 416                // KPAD * 2 bytes per gmem row

// ---------------- scratch (device globals; no allocation allowed) ----------------
__device__ __align__(16) float d_M[NRELS * D1 * D1];
__device__ __align__(16) float d_y[BATCHN * D1];
__device__ float d_stats[2 * D1];                  // BN1 sum / sumsq (atomics)
__device__ float d_bn0p[2 * 32 * D1];              // BN0 partials: 32 blocks x (sum|sumsq)

__device__ __align__(16) __half d_Af16[BATCHN * KPAD];
__device__ __align__(16) __half d_Ef16[(size_t)NENT_PAD * KPAD];

// ---------------- PTX helpers (generic-PTX-safe) ----------------
__device__ __forceinline__ uint32_t smem_u32(const void* p) {
    uint32_t a;
    asm("{ .reg .u64 t; cvta.to.shared.u64 t, %1; cvt.u32.u64 %0, t; }" : "=r"(a) : "l"(p));
    return a;
}
__device__ __forceinline__ void cp16(uint32_t dst, const void* src) {
    asm volatile("cp.async.cg.shared.global [%0], [%1], 16;" :: "r"(dst), "l"(src) : "memory");
}
__device__ __forceinline__ void cp_commit() { asm volatile("cp.async.commit_group;" ::: "memory"); }
template <int N>
__device__ __forceinline__ void cp_wait() { asm volatile("cp.async.wait_group %0;" :: "n"(N) : "memory"); }

__device__ __forceinline__ void ldx4(uint32_t& r0, uint32_t& r1, uint32_t& r2, uint32_t& r3,
                                     uint32_t addr) {
    asm volatile("ldmatrix.sync.aligned.m8n8.x4.shared.b16 {%0,%1,%2,%3}, [%4];"
                 : "=r"(r0), "=r"(r1), "=r"(r2), "=r"(r3) : "r"(addr));
}
__device__ __forceinline__ void mma16816h(float* c, const uint32_t* a, const uint32_t* b) {
    asm volatile(
        "mma.sync.aligned.m16n8k16.row.col.f32.f16.f16.f32 "
        "{%0,%1,%2,%3}, {%4,%5,%6,%7}, {%8,%9}, {%0,%1,%2,%3};"
        : "+f"(c[0]), "+f"(c[1]), "+f"(c[2]), "+f"(c[3])
        : "r"(a[0]), "r"(a[1]), "r"(a[2]), "r"(a[3]), "r"(b[0]), "r"(b[1]));
}

// ---------------- launch 1: mega-prep (independent block ranges) ----------------
#define NB_CONV 19532           // ceil(5,000,000 / 256)
#define NB_BN0  32
#define NB_BM   157             // ceil(40000 / 256)
#define NB_PREP (NB_CONV + NB_BN0 + NB_BM + 1)

__global__ void prep_kernel(const float* __restrict__ E, const int* __restrict__ e1_idx,
                            const float* __restrict__ R1, const float* __restrict__ R2,
                            const float* __restrict__ R3, const float* __restrict__ W1,
                            const float* __restrict__ W2, const float* __restrict__ W3) {
    const int bid = blockIdx.x;
    const int tid = threadIdx.x;

    if (bid < NB_CONV) {
        int f4 = bid * 256 + tid;                   // 5,000,000 float4s
        if (f4 >= (NENT * D1) / 4) return;
        int row = f4 / 50;                          // 50 float4 per row
        int col = (f4 - row * 50) * 4;
        float4 v = *(const float4*)(E + (size_t)f4 * 4);
        __half2 h01 = __floats2half2_rn(v.x, v.y);
        __half2 h23 = __floats2half2_rn(v.z, v.w);
        size_t o = (size_t)row * KPAD + col;
        *(__half2*)(d_Ef16 + o)     = h01;
        *(__half2*)(d_Ef16 + o + 2) = h23;
        return;
    }
    if (bid < NB_CONV + NB_BN0) {
        int b2 = bid - NB_CONV;                     // 0..31, covers 32 batch rows
        int j = tid;
        if (j >= D1) return;
        float s = 0.f, ss = 0.f;
#pragma unroll 8
        for (int r = 0; r < 32; r++) {
            int e1 = e1_idx[b2 * 32 + r];
            float v = E[e1 * D1 + j];
            s += v; ss += v * v;
        }
        d_bn0p[b2 * D1 + j] = s;
        d_bn0p[32 * D1 + b2 * D1 + j] = ss;
        return;
    }
    if (bid < NB_CONV + NB_BN0 + NB_BM) {
        int e = (bid - NB_CONV - NB_BN0) * 256 + tid;
        if (e >= D1 * D1) return;
        int j = e / D1, k = e % D1;
        int a = j < k ? j : k;
        int b = j < k ? k : j;
        int sidx = a * (2 * D1 - a + 1) / 2 + (b - a);
        float asign = 0.f; int aoff = 0;
        if (j < k)      { asign =  1.f; aoff = (2 * D1 - j - 1) * j / 2 + (k - j) - 1; }
        else if (j > k) { asign = -1.f; aoff = (2 * D1 - k - 1) * k / 2 + (j - k) - 1; }

        float m[NRELS];
#pragma unroll
        for (int r = 0; r < NRELS; r++) m[r] = 0.f;

#pragma unroll 5
        for (int s = 0; s < 30; s++) {
            float w1 = __ldg(W1 + s * 20100 + sidx);
            m[1]  = fmaf(__ldg(R1 + s),        w1, m[1]);
            m[8]  = fmaf(__ldg(R1 + 30 + s),   w1, m[8]);
            m[10] = fmaf(__ldg(R1 + 60 + s),   w1, m[10]);
            m[0]  = fmaf(__ldg(R3 + s),        w1, m[0]);
            m[3]  = fmaf(__ldg(R3 + 80 + s),   w1, m[3]);
            m[9]  = fmaf(__ldg(R3 + 160 + s),  w1, m[9]);
        }
        if (asign != 0.f) {
#pragma unroll 5
            for (int s = 0; s < 30; s++) {
                float w2 = asign * __ldg(W2 + s * 19900 + aoff);
                m[2] = fmaf(__ldg(R2 + s),        w2, m[2]);
                m[4] = fmaf(__ldg(R2 + 30 + s),   w2, m[4]);
                m[5] = fmaf(__ldg(R2 + 60 + s),   w2, m[5]);
                m[6] = fmaf(__ldg(R2 + 90 + s),   w2, m[6]);
                m[7] = fmaf(__ldg(R2 + 120 + s),  w2, m[7]);
                m[0] = fmaf(__ldg(R3 + 30 + s),   w2, m[0]);
                m[3] = fmaf(__ldg(R3 + 110 + s),  w2, m[3]);
                m[9] = fmaf(__ldg(R3 + 190 + s),  w2, m[9]);
            }
        }
#pragma unroll 5
        for (int o = 0; o < 20; o++) {
            float w3 = __ldg(W3 + o * 40000 + e);
            m[0] = fmaf(__ldg(R3 + 60 + o),   w3, m[0]);
            m[3] = fmaf(__ldg(R3 + 140 + o),  w3, m[3]);
            m[9] = fmaf(__ldg(R3 + 220 + o),  w3, m[9]);
        }
#pragma unroll
        for (int r = 0; r < NRELS; r++) d_M[r * 40000 + e] = m[r];
        return;
    }
    for (int t = tid; t < 2 * D1; t += 256) d_stats[t] = 0.f;
}

// ---------------- launch 2: y = M[r]^T bn0(E[e1]); BN1 atomics ----------------
__global__ void mid_kernel(const float* __restrict__ E, const int* __restrict__ e1_idx,
                           const int* __restrict__ r_idx,
                           const float* __restrict__ g0, const float* __restrict__ b0) {
    __shared__ float xs[D1];
    int b = blockIdx.x;
    int t = threadIdx.x;
    if (t < D1) {
        float s = 0.f, ss = 0.f;
#pragma unroll 8
        for (int i = 0; i < 32; i++) {
            s  += d_bn0p[i * D1 + t];
            ss += d_bn0p[32 * D1 + i * D1 + t];
        }
        float mean = s * (1.f / BATCHN);
        float var  = ss * (1.f / BATCHN) - mean * mean;
        float inv  = rsqrtf(var + 1e-5f);
        int e1 = e1_idx[b];
        xs[t] = (E[e1 * D1 + t] - mean) * inv * g0[t] + b0[t];
    }
    __syncthreads();
    if (t < D1) {
        const float* M = d_M + r_idx[b] * 40000;
        // 2 independent accumulator chains to break the 4-cyc FMA dependency
        float acc0 = 0.f, acc1 = 0.f;
#pragma unroll 8
        for (int jj = 0; jj < D1; jj += 2) {
            acc0 = fmaf(M[jj * D1 + t],       xs[jj],     acc0);
            acc1 = fmaf(M[(jj + 1) * D1 + t], xs[jj + 1], acc1);
        }
        float acc = acc0 + acc1;
        d_y[b * D1 + t] = acc;
        atomicAdd(&d_stats[t], acc);
        atomicAdd(&d_stats[D1 + t], acc * acc);
    }
}

// ---------------- launch 3: BN1 + fp16 convert A ----------------
__global__ void bn1_convA_kernel(const float* __restrict__ g1, const float* __restrict__ b1) {
    int row = blockIdx.x;
    int col = threadIdx.x;
    if (col >= D1) return;
    float mean = d_stats[col] * (1.f / BATCHN);
    float var  = d_stats[D1 + col] * (1.f / BATCHN) - mean * mean;
    float inv  = rsqrtf(var + 1e-5f);
    float v = (d_y[row * D1 + col] - mean) * inv * g1[col] + b1[col];
    d_Af16[row * KPAD + col] = __float2half_rn(v);
}

// ---------------- sigmoid: FMUL + MUFU.EX2 + FADD + MUFU.RCP (4 issue slots) ----------------
// No clamp needed: exp(-x) -> inf for very negative x gives rcp -> 0 (correct);
// exp(-x) -> 0 for very positive x gives rcp(1) = 1 (correct).
__device__ __forceinline__ float sigmoidf_fast(float x) {
    float w = 1.0f + __expf(-x);
    float r;
    asm("rcp.approx.f32 %0, %1;" : "=f"(r) : "f"(w));
    return r;
}

// ---------------- launch 4: single-term fp16 mma GEMM + sigmoid ----------------
// CTA 128x128, 512 threads / 16 warps (4m x 4n), warp tile 32x32, K = 13 x k16.
// __launch_bounds__(512, 2): 2 CTAs co-reside per SM.
// smem per stage: A + B, each 128 rows x 48B (32B data + 16B pad) = 6144B.
#define NSTAGE 5
#define MAT_B  6144
#define STAGE_B (2 * MAT_B)          // 12288
#define SMEM_GEMM (NSTAGE * STAGE_B) // 61440 (x2 CTAs = 120KB < 228KB)

__global__ __launch_bounds__(512, 2)
void gemm_mma_kernel(float* __restrict__ out) {
    extern __shared__ __align__(128) char smem[];
    const uint32_t sb = smem_u32(smem);
    const int tid  = threadIdx.x;
    const int lane = tid & 31;
    const int wid  = tid >> 5;
    const int wm   = wid >> 2;       // 0..3  (32 rows each)
    const int wn   = wid & 3;        // 0..3  (32 cols each)

    const int m0 = blockIdx.y << 7;
    const int n0 = blockIdx.x << 7;

    // ---- cp.async: 2 groups of 256 threads -> one matrix each, 1 x 16B per thread ----
    const int mt = tid >> 8;         // 0:A 1:B
    const int c0 = tid & 255;
    const char* gbase = (mt == 0)
        ? (const char*)d_Af16 + (size_t)m0 * ROWB
        : (const char*)d_Ef16 + (size_t)n0 * ROWB;
    const uint32_t smat = sb + mt * MAT_B;
    const int lrow = c0 >> 1, lhalf = c0 & 1;

    auto issue = [&](int step, int slot) {
        cp16(smat + slot * STAGE_B + lrow * 48 + lhalf * 16,
             gbase + (size_t)lrow * ROWB + step * 32 + lhalf * 16);
        cp_commit();
    };

    // ---- ldmatrix per-lane offsets (48B rows -> conflict-free) ----
    const int g  = lane >> 3;
    const int l8 = lane & 7;
    const uint32_t a_off = (uint32_t)((wm * 32 + (g & 1) * 8 + l8) * 48 + (g >> 1) * 16);
    const uint32_t b_off = (uint32_t)(MAT_B + (wn * 32 + (g >> 1) * 8 + l8) * 48 + (g & 1) * 16);

    float acc[2][4][4];
#pragma unroll
    for (int mi = 0; mi < 2; mi++)
#pragma unroll
        for (int ni = 0; ni < 4; ni++)
#pragma unroll
            for (int r = 0; r < 4; r++) acc[mi][ni][r] = 0.f;

    uint32_t ah[2][4], bh[4][2];

    auto load_frags = [&](int slot) {
        uint32_t base = sb + slot * STAGE_B;
#pragma unroll
        for (int mi = 0; mi < 2; mi++)
            ldx4(ah[mi][0], ah[mi][1], ah[mi][2], ah[mi][3], base + a_off + mi * 768);
#pragma unroll
        for (int p = 0; p < 2; p++)
            ldx4(bh[2*p][0], bh[2*p][1], bh[2*p+1][0], bh[2*p+1][1], base + b_off + p * 768);
    };

    auto do_mma = [&]() {
#pragma unroll
        for (int mi = 0; mi < 2; mi++)
#pragma unroll
            for (int ni = 0; ni < 4; ni++)
                mma16816h(acc[mi][ni], ah[mi], bh[ni]);
    };

    // ---- pipeline: prologue 4 stages, steady wait<3>, peeled tail; fully unrolled ----
    issue(0, 0); issue(1, 1); issue(2, 2); issue(3, 3);

#pragma unroll
    for (int i = 0; i < 10; i++) {
        cp_wait<3>();
        __syncthreads();
        load_frags(i % NSTAGE);
        if (i < 9) issue(i + 4, (i + 4) % NSTAGE);
        do_mma();
    }
    cp_wait<2>(); __syncthreads(); load_frags(10 % NSTAGE); do_mma();
    cp_wait<1>(); __syncthreads(); load_frags(11 % NSTAGE); do_mma();
    cp_wait<0>(); __syncthreads(); load_frags(12 % NSTAGE); do_mma();

    // ---- epilogue: sigmoid + float2 stores ----
    const int mrow0 = m0 + wm * 32 + (lane >> 2);
    const int ncol0 = n0 + wn * 32 + ((lane & 3) << 1);
#pragma unroll
    for (int mi = 0; mi < 2; mi++) {
#pragma unroll
        for (int ni = 0; ni < 4; ni++) {
            int gn = ncol0 + ni * 8;
            if (gn < NENT) {
                int gm = mrow0 + mi * 16;
                float2 v0, v1;
                v0.x = sigmoidf_fast(acc[mi][ni][0]);
                v0.y = sigmoidf_fast(acc[mi][ni][1]);
                v1.x = sigmoidf_fast(acc[mi][ni][2]);
                v1.y = sigmoidf_fast(acc[mi][ni][3]);
                *(float2*)(out + (size_t)gm * NENT + gn) = v0;
                *(float2*)(out + (size_t)(gm + 8) * NENT + gn) = v1;
            }
        }
    }
}

// ---------------- launch ----------------
extern "C" void kernel_launch(void* const* d_in, const int* in_sizes, int n_in,
                              void* d_out, int out_size) {
    const float* E  = (const float*)d_in[0];
    const float* R1 = (const float*)d_in[1];
    const float* R2 = (const float*)d_in[2];
    const float* R3 = (const float*)d_in[3];
    const float* W1 = (const float*)d_in[4];
    const float* W2 = (const float*)d_in[5];
    const float* W3 = (const float*)d_in[6];
    const float* g0 = (const float*)d_in[7];
    const float* b0 = (const float*)d_in[8];
    const float* g1 = (const float*)d_in[9];
    const float* b1 = (const float*)d_in[10];
    const int* e1_idx = (const int*)d_in[11];
    const int* r_idx  = (const int*)d_in[12];
    float* out = (float*)d_out;

    cudaFuncSetAttribute(gemm_mma_kernel, cudaFuncAttributeMaxDynamicSharedMemorySize,
                         SMEM_GEMM);

    prep_kernel<<<NB_PREP, 256>>>(E, e1_idx, R1, R2, R3, W1, W2, W3);   // 1
    mid_kernel<<<BATCHN, 256>>>(E, e1_idx, r_idx, g0, b0);              // 2
    bn1_convA_kernel<<<BATCHN, 256>>>(g1, b1);                          // 3
    gemm_mma_kernel<<<dim3(NTILES, MTILES), 512, SMEM_GEMM>>>(out);     // 4
}